// round 3
// baseline (speedup 1.0000x reference)
#include <cuda_runtime.h>

#define N_NODES 50000
#define N_EDGES 800000
#define C_IN   512
#define C_H1   512
#define C_OUT  256

// ---------------- device scratch (no allocations allowed) ----------------
__device__ __align__(16) float g_T[(size_t)N_NODES * C_H1];   // GEMM output buffer
__device__ __align__(16) float g_H[(size_t)N_NODES * C_H1];   // hidden state
__device__ float g_dinv[N_NODES];
__device__ int   g_cnt[N_NODES];
__device__ int   g_cnt2[N_NODES];
__device__ int   g_rowptr[N_NODES + 1];
__device__ int   g_colsrc[N_EDGES];
__device__ float g_norm[N_EDGES];
__device__ int   g_is64;

// edge_index has 2*N_EDGES logical elements: [src(0..E-1), dst(E..2E-1)]
__device__ __forceinline__ int edge_at(const void* ei, long long idx) {
    if (g_is64) {
        long long v = ((const long long*)ei)[idx];
        return (int)v;
    } else {
        return ((const int*)ei)[idx];
    }
}

// ---------------- dtype sniffer ----------------
// If data is int64 with values in [0, 50000), every odd 32-bit word is 0.
__global__ void k_detect(const void* ei) {
    const int* w = (const int*)ei;
    unsigned acc = 0;
    for (int i = 1; i < 4096; i += 2) acc |= (unsigned)w[i];
    g_is64 = (acc == 0) ? 1 : 0;
}

// ---------------- graph prep ----------------
__global__ void k_zero_counts() {
    int i = blockIdx.x * blockDim.x + threadIdx.x;
    if (i < N_NODES) { g_cnt[i] = 0; g_cnt2[i] = 0; }
}

__global__ void k_count(const void* __restrict__ ei) {
    int e = blockIdx.x * blockDim.x + threadIdx.x;
    if (e < N_EDGES) {
        int d = edge_at(ei, (long long)N_EDGES + e);
        if (d >= 0 && d < N_NODES) atomicAdd(&g_cnt[d], 1);
    }
}

__global__ void k_dinv() {
    int i = blockIdx.x * blockDim.x + threadIdx.x;
    if (i < N_NODES) g_dinv[i] = rsqrtf((float)g_cnt[i] + 1.0f);  // +1 self loop
}

// single-block exclusive scan of g_cnt -> g_rowptr
__global__ void k_scan() {
    const int T = 1024;
    int tid = threadIdx.x;
    const int chunk = (N_NODES + T - 1) / T;
    int beg = tid * chunk;
    int end = min(beg + chunk, N_NODES);
    int sum = 0;
    for (int i = beg; i < end; i++) sum += g_cnt[i];
    __shared__ int s[T];
    s[tid] = sum;
    __syncthreads();
    for (int off = 1; off < T; off <<= 1) {
        int v = (tid >= off) ? s[tid - off] : 0;
        __syncthreads();
        s[tid] += v;
        __syncthreads();
    }
    int run = (tid > 0) ? s[tid - 1] : 0;
    for (int i = beg; i < end; i++) { g_rowptr[i] = run; run += g_cnt[i]; }
    if (tid == T - 1) g_rowptr[N_NODES] = N_EDGES;
}

__global__ void k_scatter(const void* __restrict__ ei) {
    int e = blockIdx.x * blockDim.x + threadIdx.x;
    if (e < N_EDGES) {
        int s = edge_at(ei, e);
        int d = edge_at(ei, (long long)N_EDGES + e);
        if (s < 0 || s >= N_NODES || d < 0 || d >= N_NODES) return;
        int pos = g_rowptr[d] + atomicAdd(&g_cnt2[d], 1);
        if (pos >= 0 && pos < N_EDGES) {
            g_colsrc[pos] = s;
            g_norm[pos] = g_dinv[s] * g_dinv[d];
        }
    }
}

// ---------------- dense GEMM: g_T[M,N] = A[M,K] @ B[K,N]  (fp32 SIMT tiled) ----------------
// A = A_ext if non-null, else g_H. block 16x16 threads, tile 64x64x16, 4x4 microtile.
__global__ void k_gemm(const float* __restrict__ A_ext, const float* __restrict__ B,
                       int M, int N, int K) {
    const float* A = A_ext ? A_ext : (const float*)g_H;
    float* C = g_T;

    __shared__ float As[64][16];
    __shared__ float Bs[16][64];
    int tid = threadIdx.y * 16 + threadIdx.x;
    int row0 = blockIdx.y * 64;
    int col0 = blockIdx.x * 64;

    int la_r = (tid * 4) / 16, la_c = (tid * 4) % 16;
    int lb_r = (tid * 4) / 64, lb_c = (tid * 4) % 64;

    float acc[4][4];
#pragma unroll
    for (int i = 0; i < 4; i++)
#pragma unroll
        for (int j = 0; j < 4; j++) acc[i][j] = 0.0f;

    for (int kt = 0; kt < K; kt += 16) {
        int ar = row0 + la_r;
        float4 av = (ar < M) ? *(const float4*)&A[(size_t)ar * K + kt + la_c]
                             : make_float4(0.f, 0.f, 0.f, 0.f);
        *(float4*)&As[la_r][la_c] = av;
        float4 bv = *(const float4*)&B[(size_t)(kt + lb_r) * N + col0 + lb_c];
        *(float4*)&Bs[lb_r][lb_c] = bv;
        __syncthreads();
#pragma unroll
        for (int kk = 0; kk < 16; kk++) {
            float a[4], b[4];
#pragma unroll
            for (int i = 0; i < 4; i++) a[i] = As[threadIdx.y * 4 + i][kk];
#pragma unroll
            for (int j = 0; j < 4; j++) b[j] = Bs[kk][threadIdx.x * 4 + j];
#pragma unroll
            for (int i = 0; i < 4; i++)
#pragma unroll
                for (int j = 0; j < 4; j++) acc[i][j] += a[i] * b[j];
        }
        __syncthreads();
    }
#pragma unroll
    for (int i = 0; i < 4; i++) {
        int r = row0 + threadIdx.y * 4 + i;
        if (r < M) {
#pragma unroll
            for (int j = 0; j < 4; j++)
                C[(size_t)r * N + col0 + threadIdx.x * 4 + j] = acc[i][j];
        }
    }
}

// ---------------- CSR SpMM with fused epilogue ----------------
// one block per node; C/4 threads, each owns a float4 of channels
template <int C, bool RELU, bool RES, bool TO_OUT>
__global__ void k_spmm(const float* __restrict__ bias, float* __restrict__ out) {
    constexpr int V4 = C / 4;
    int i = blockIdx.x;
    int tid = threadIdx.x;
    const float4* T4 = (const float4*)g_T;

    float di = g_dinv[i];
    float wself = di * di;
    float4 t = T4[(size_t)i * V4 + tid];
    float4 acc = make_float4(t.x * wself, t.y * wself, t.z * wself, t.w * wself);

    int e = g_rowptr[i];
    int end = g_rowptr[i + 1];
    for (; e < end; e++) {
        int s = g_colsrc[e];
        float w = g_norm[e];
        float4 v = T4[(size_t)s * V4 + tid];
        acc.x += w * v.x;
        acc.y += w * v.y;
        acc.z += w * v.z;
        acc.w += w * v.w;
    }

    float4 b = ((const float4*)bias)[tid];
    acc.x += b.x; acc.y += b.y; acc.z += b.z; acc.w += b.w;

    if (RELU) {
        acc.x = fmaxf(acc.x, 0.f);
        acc.y = fmaxf(acc.y, 0.f);
        acc.z = fmaxf(acc.z, 0.f);
        acc.w = fmaxf(acc.w, 0.f);
    }

    if (RES) {
        float4 h = ((const float4*)g_H)[(size_t)i * V4 + tid];
        acc.x += h.x; acc.y += h.y; acc.z += h.z; acc.w += h.w;
    }

    float4* D = TO_OUT ? (float4*)out : (float4*)g_H;
    D[(size_t)i * V4 + tid] = acc;
}

// ---------------- launch ----------------
extern "C" void kernel_launch(void* const* d_in, const int* in_sizes, int n_in,
                              void* d_out, int out_size) {
    const float* x      = (const float*)d_in[0];
    const void*  ei     = d_in[1];                 // int32 or int64, sniffed on device
    const float* W1     = (const float*)d_in[2];
    const float* b1     = (const float*)d_in[3];
    const float* Wr     = (const float*)d_in[4];
    const float* br     = (const float*)d_in[5];
    const float* Wx     = (const float*)d_in[6];
    const float* bx     = (const float*)d_in[7];
    float* out          = (float*)d_out;

    // graph prep
    k_detect<<<1, 1>>>(ei);
    k_zero_counts<<<(N_NODES + 255) / 256, 256>>>();
    k_count<<<(N_EDGES + 255) / 256, 256>>>(ei);
    k_dinv<<<(N_NODES + 255) / 256, 256>>>();
    k_scan<<<1, 1024>>>();
    k_scatter<<<(N_EDGES + 255) / 256, 256>>>(ei);

    dim3 gthr(16, 16);
    dim3 ggrid512(C_H1 / 64, (N_NODES + 63) / 64);
    dim3 ggrid256(C_OUT / 64, (N_NODES + 63) / 64);

    // layer 0: H = relu(agg(x @ W1) + b1)
    k_gemm<<<ggrid512, gthr>>>(x, W1, N_NODES, C_H1, C_IN);
    k_spmm<C_H1, true, false, false><<<N_NODES, C_H1 / 4>>>(b1, out);

    // 4 residual layers: H = relu(agg(H @ Wr) + br) + H
    for (int l = 0; l < 4; l++) {
        k_gemm<<<ggrid512, gthr>>>(nullptr, Wr, N_NODES, C_H1, C_H1);
        k_spmm<C_H1, true, true, false><<<N_NODES, C_H1 / 4>>>(br, out);
    }

    // final: out = agg(H @ Wx) + bx
    k_gemm<<<ggrid256, gthr>>>(nullptr, Wx, N_NODES, C_OUT, C_H1);
    k_spmm<C_OUT, false, false, true><<<N_NODES, C_OUT / 4>>>(bx, out);
}

// round 4
// speedup vs baseline: 1.3387x; 1.3387x over previous
#include <cuda_runtime.h>
#include <cuda_bf16.h>

#define N_NODES 50000
#define N_EDGES 800000
#define C_IN   512
#define C_H1   512
#define C_OUT  256

// ---------------- device scratch (no allocations allowed) ----------------
__device__ __align__(16) float g_T[(size_t)N_NODES * C_H1];   // GEMM output buffer
__device__ __align__(16) float g_H[(size_t)N_NODES * C_H1];   // hidden state
__device__ float g_dinv[N_NODES];
__device__ int   g_cnt[N_NODES];
__device__ int   g_cnt2[N_NODES];
__device__ int   g_rowptr[N_NODES + 1];
__device__ int   g_colsrc[N_EDGES];
__device__ float g_norm[N_EDGES];
__device__ int   g_is64;

// edge_index has 2*N_EDGES logical elements: [src(0..E-1), dst(E..2E-1)]
__device__ __forceinline__ int edge_at(const void* ei, long long idx) {
    if (g_is64) return (int)((const long long*)ei)[idx];
    return ((const int*)ei)[idx];
}

// ---------------- dtype sniffer ----------------
__global__ void k_detect(const void* ei) {
    const int* w = (const int*)ei;
    unsigned acc = 0;
    for (int i = 1; i < 4096; i += 2) acc |= (unsigned)w[i];
    g_is64 = (acc == 0) ? 1 : 0;
}

// ---------------- graph prep ----------------
__global__ void k_zero_counts() {
    int i = blockIdx.x * blockDim.x + threadIdx.x;
    if (i < N_NODES) { g_cnt[i] = 0; g_cnt2[i] = 0; }
}

__global__ void k_count(const void* __restrict__ ei) {
    int e = blockIdx.x * blockDim.x + threadIdx.x;
    if (e < N_EDGES) {
        int d = edge_at(ei, (long long)N_EDGES + e);
        if (d >= 0 && d < N_NODES) atomicAdd(&g_cnt[d], 1);
    }
}

__global__ void k_dinv() {
    int i = blockIdx.x * blockDim.x + threadIdx.x;
    if (i < N_NODES) g_dinv[i] = rsqrtf((float)g_cnt[i] + 1.0f);
}

__global__ void k_scan() {
    const int T = 1024;
    int tid = threadIdx.x;
    const int chunk = (N_NODES + T - 1) / T;
    int beg = tid * chunk;
    int end = min(beg + chunk, N_NODES);
    int sum = 0;
    for (int i = beg; i < end; i++) sum += g_cnt[i];
    __shared__ int s[T];
    s[tid] = sum;
    __syncthreads();
    for (int off = 1; off < T; off <<= 1) {
        int v = (tid >= off) ? s[tid - off] : 0;
        __syncthreads();
        s[tid] += v;
        __syncthreads();
    }
    int run = (tid > 0) ? s[tid - 1] : 0;
    for (int i = beg; i < end; i++) { g_rowptr[i] = run; run += g_cnt[i]; }
    if (tid == T - 1) g_rowptr[N_NODES] = N_EDGES;
}

__global__ void k_scatter(const void* __restrict__ ei) {
    int e = blockIdx.x * blockDim.x + threadIdx.x;
    if (e < N_EDGES) {
        int s = edge_at(ei, e);
        int d = edge_at(ei, (long long)N_EDGES + e);
        if (s < 0 || s >= N_NODES || d < 0 || d >= N_NODES) return;
        int pos = g_rowptr[d] + atomicAdd(&g_cnt2[d], 1);
        if (pos >= 0 && pos < N_EDGES) {
            g_colsrc[pos] = s;
            g_norm[pos] = g_dinv[s] * g_dinv[d];
        }
    }
}

// ---------------- tensor-core GEMM: g_T[M,N] = A[M,K] @ B[K,N] ----------------
// bf16x3 compensated: a = a_hi + a_lo; acc += ah*bh + ah*bl + al*bh  (fp32 accum)
// Tile 128x64x32, 256 threads = 8 warps; warp w owns rows [16w,16w+16) x all 64 cols.
#define BM 128
#define BN 64
#define BK 32
#define SKEW 8          // pad to 40 bf16 per row -> conflict-free fragment loads

__device__ __forceinline__ void mma_bf16(float* c, const unsigned* a, const unsigned* b) {
    asm volatile(
        "mma.sync.aligned.m16n8k16.row.col.f32.bf16.bf16.f32 "
        "{%0,%1,%2,%3}, {%4,%5,%6,%7}, {%8,%9}, {%0,%1,%2,%3};"
        : "+f"(c[0]), "+f"(c[1]), "+f"(c[2]), "+f"(c[3])
        : "r"(a[0]), "r"(a[1]), "r"(a[2]), "r"(a[3]), "r"(b[0]), "r"(b[1]));
}

__device__ __forceinline__ void split_bf16(float v, __nv_bfloat16& hi, __nv_bfloat16& lo) {
    hi = __float2bfloat16(v);
    lo = __float2bfloat16(v - __bfloat162float(hi));
}

__global__ void __launch_bounds__(256, 2)
k_gemm_tc(const float* __restrict__ A_ext, const float* __restrict__ B,
          int M, int N, int K) {
    const float* A = A_ext ? A_ext : (const float*)g_H;
    float* C = g_T;

    __shared__ __nv_bfloat16 sAh[BM][BK + SKEW];
    __shared__ __nv_bfloat16 sAl[BM][BK + SKEW];
    __shared__ __nv_bfloat16 sBh[BN][BK + SKEW];   // transposed: [n][k]
    __shared__ __nv_bfloat16 sBl[BN][BK + SKEW];

    int tid  = threadIdx.x;
    int w    = tid >> 5;
    int lane = tid & 31;
    int g    = lane >> 2;      // group id 0..7
    int t    = lane & 3;       // thread-in-group 0..3

    int row0 = blockIdx.y * BM;
    int col0 = blockIdx.x * BN;
    int wrow = w * 16;

    float acc[8][4];
#pragma unroll
    for (int n = 0; n < 8; n++)
#pragma unroll
        for (int j = 0; j < 4; j++) acc[n][j] = 0.0f;

    for (int kt = 0; kt < K; kt += BK) {
        // ---- load A 128x32 fp32 -> split bf16 (4 float4 per thread) ----
#pragma unroll
        for (int it = 0; it < 4; it++) {
            int idx = tid + it * 256;          // 0..1023 float4s
            int r  = idx >> 3;                 // row 0..127
            int c4 = idx & 7;                  // float4 within row
            float4 v = make_float4(0.f, 0.f, 0.f, 0.f);
            if (row0 + r < M)
                v = *(const float4*)&A[(size_t)(row0 + r) * K + kt + c4 * 4];
            __nv_bfloat16 h0, l0, h1, l1, h2, l2, h3, l3;
            split_bf16(v.x, h0, l0); split_bf16(v.y, h1, l1);
            split_bf16(v.z, h2, l2); split_bf16(v.w, h3, l3);
            int c = c4 * 4;
            sAh[r][c] = h0; sAh[r][c+1] = h1; sAh[r][c+2] = h2; sAh[r][c+3] = h3;
            sAl[r][c] = l0; sAl[r][c+1] = l1; sAl[r][c+2] = l2; sAl[r][c+3] = l3;
        }
        // ---- load B 32x64 fp32 -> split bf16 transposed (2 float4 per thread) ----
#pragma unroll
        for (int it = 0; it < 2; it++) {
            int idx = tid + it * 256;          // 0..511 float4s
            int r  = idx >> 4;                 // k row 0..31
            int c4 = idx & 15;                 // float4 within 64 cols
            float4 v = *(const float4*)&B[(size_t)(kt + r) * N + col0 + c4 * 4];
            __nv_bfloat16 h, l;
            int c = c4 * 4;
            split_bf16(v.x, h, l); sBh[c  ][r] = h; sBl[c  ][r] = l;
            split_bf16(v.y, h, l); sBh[c+1][r] = h; sBl[c+1][r] = l;
            split_bf16(v.z, h, l); sBh[c+2][r] = h; sBl[c+2][r] = l;
            split_bf16(v.w, h, l); sBh[c+3][r] = h; sBl[c+3][r] = l;
        }
        __syncthreads();

#pragma unroll
        for (int ks = 0; ks < BK; ks += 16) {
            unsigned ah[4], al[4];
            ah[0] = *(const unsigned*)&sAh[wrow + g    ][ks + 2*t    ];
            ah[1] = *(const unsigned*)&sAh[wrow + g + 8][ks + 2*t    ];
            ah[2] = *(const unsigned*)&sAh[wrow + g    ][ks + 2*t + 8];
            ah[3] = *(const unsigned*)&sAh[wrow + g + 8][ks + 2*t + 8];
            al[0] = *(const unsigned*)&sAl[wrow + g    ][ks + 2*t    ];
            al[1] = *(const unsigned*)&sAl[wrow + g + 8][ks + 2*t    ];
            al[2] = *(const unsigned*)&sAl[wrow + g    ][ks + 2*t + 8];
            al[3] = *(const unsigned*)&sAl[wrow + g + 8][ks + 2*t + 8];
#pragma unroll
            for (int n = 0; n < 8; n++) {
                unsigned bh[2], bl[2];
                bh[0] = *(const unsigned*)&sBh[n*8 + g][ks + 2*t    ];
                bh[1] = *(const unsigned*)&sBh[n*8 + g][ks + 2*t + 8];
                bl[0] = *(const unsigned*)&sBl[n*8 + g][ks + 2*t    ];
                bl[1] = *(const unsigned*)&sBl[n*8 + g][ks + 2*t + 8];
                mma_bf16(acc[n], ah, bh);
                mma_bf16(acc[n], ah, bl);
                mma_bf16(acc[n], al, bh);
            }
        }
        __syncthreads();
    }

    // ---- epilogue ----
#pragma unroll
    for (int n = 0; n < 8; n++) {
        int col = col0 + n * 8 + 2 * t;
        int r0 = row0 + wrow + g;
        int r1 = r0 + 8;
        if (r0 < M) {
            C[(size_t)r0 * N + col]     = acc[n][0];
            C[(size_t)r0 * N + col + 1] = acc[n][1];
        }
        if (r1 < M) {
            C[(size_t)r1 * N + col]     = acc[n][2];
            C[(size_t)r1 * N + col + 1] = acc[n][3];
        }
    }
}

// ---------------- CSR SpMM with fused epilogue ----------------
template <int C, bool RELU, bool RES, bool TO_OUT>
__global__ void k_spmm(const float* __restrict__ bias, float* __restrict__ out) {
    constexpr int V4 = C / 4;
    int i = blockIdx.x;
    int tid = threadIdx.x;
    const float4* T4 = (const float4*)g_T;

    float di = g_dinv[i];
    float wself = di * di;
    float4 tv = T4[(size_t)i * V4 + tid];
    float4 acc = make_float4(tv.x * wself, tv.y * wself, tv.z * wself, tv.w * wself);

    int e = g_rowptr[i];
    int end = g_rowptr[i + 1];
    for (; e < end; e++) {
        int s = g_colsrc[e];
        float w = g_norm[e];
        float4 v = T4[(size_t)s * V4 + tid];
        acc.x += w * v.x; acc.y += w * v.y; acc.z += w * v.z; acc.w += w * v.w;
    }

    float4 b = ((const float4*)bias)[tid];
    acc.x += b.x; acc.y += b.y; acc.z += b.z; acc.w += b.w;

    if (RELU) {
        acc.x = fmaxf(acc.x, 0.f); acc.y = fmaxf(acc.y, 0.f);
        acc.z = fmaxf(acc.z, 0.f); acc.w = fmaxf(acc.w, 0.f);
    }
    if (RES) {
        float4 h = ((const float4*)g_H)[(size_t)i * V4 + tid];
        acc.x += h.x; acc.y += h.y; acc.z += h.z; acc.w += h.w;
    }
    float4* D = TO_OUT ? (float4*)out : (float4*)g_H;
    D[(size_t)i * V4 + tid] = acc;
}

// ---------------- launch ----------------
extern "C" void kernel_launch(void* const* d_in, const int* in_sizes, int n_in,
                              void* d_out, int out_size) {
    const float* x  = (const float*)d_in[0];
    const void*  ei = d_in[1];
    const float* W1 = (const float*)d_in[2];
    const float* b1 = (const float*)d_in[3];
    const float* Wr = (const float*)d_in[4];
    const float* br = (const float*)d_in[5];
    const float* Wx = (const float*)d_in[6];
    const float* bx = (const float*)d_in[7];
    float* out      = (float*)d_out;

    k_detect<<<1, 1>>>(ei);
    k_zero_counts<<<(N_NODES + 255) / 256, 256>>>();
    k_count<<<(N_EDGES + 255) / 256, 256>>>(ei);
    k_dinv<<<(N_NODES + 255) / 256, 256>>>();
    k_scan<<<1, 1024>>>();
    k_scatter<<<(N_EDGES + 255) / 256, 256>>>(ei);

    dim3 g512(C_H1 / BN, (N_NODES + BM - 1) / BM);
    dim3 g256(C_OUT / BN, (N_NODES + BM - 1) / BM);

    k_gemm_tc<<<g512, 256>>>(x, W1, N_NODES, C_H1, C_IN);
    k_spmm<C_H1, true, false, false><<<N_NODES, C_H1 / 4>>>(b1, out);

    for (int l = 0; l < 4; l++) {
        k_gemm_tc<<<g512, 256>>>(nullptr, Wr, N_NODES, C_H1, C_H1);
        k_spmm<C_H1, true, true, false><<<N_NODES, C_H1 / 4>>>(br, out);
    }

    k_gemm_tc<<<g256, 256>>>(nullptr, Wx, N_NODES, C_OUT, C_H1);
    k_spmm<C_OUT, false, false, true><<<N_NODES, C_OUT / 4>>>(bx, out);
}

// round 7
// speedup vs baseline: 1.6227x; 1.2122x over previous
#include <cuda_runtime.h>
#include <cuda_bf16.h>

#define N_NODES 50000
#define N_EDGES 800000
#define C_IN   512
#define C_H1   512
#define C_OUT  256

typedef __nv_bfloat16 bf16;

// ---------------- device scratch (no allocations allowed) ----------------
__device__ __align__(16) float g_T[(size_t)N_NODES * C_H1];   // GEMM output
__device__ __align__(16) float g_H[(size_t)N_NODES * C_H1];   // hidden (fp32, for residual)
__device__ __align__(16) bf16  g_Hh[(size_t)N_NODES * C_H1];  // hidden hi (GEMM A)
__device__ __align__(16) bf16  g_Hl[(size_t)N_NODES * C_H1];  // hidden lo
__device__ __align__(16) bf16  g_W1h[C_IN * C_H1],  g_W1l[C_IN * C_H1];   // [N][K] transposed
__device__ __align__(16) bf16  g_Wrh[C_H1 * C_H1],  g_Wrl[C_H1 * C_H1];
__device__ __align__(16) bf16  g_Wxh[C_H1 * C_OUT], g_Wxl[C_H1 * C_OUT];
__device__ float g_dinv[N_NODES];
__device__ int   g_cnt[N_NODES];
__device__ int   g_cnt2[N_NODES];
__device__ int   g_rowptr[N_NODES + 1];
__device__ int   g_colsrc[N_EDGES];
__device__ float g_norm[N_EDGES];
__device__ int   g_is64;

__device__ __forceinline__ int edge_at(const void* ei, long long idx) {
    if (g_is64) return (int)((const long long*)ei)[idx];
    return ((const int*)ei)[idx];
}

__device__ __forceinline__ void split_bf16(float v, bf16& hi, bf16& lo) {
    hi = __float2bfloat16(v);
    lo = __float2bfloat16(v - __bfloat162float(hi));
}

// ---------------- dtype sniffer (parallel) ----------------
__global__ void k_detect(const void* ei) {
    const int* w = (const int*)ei;
    __shared__ unsigned s[256];
    unsigned acc = 0;
    for (int i = threadIdx.x; i < 2048; i += 256) acc |= (unsigned)w[2 * i + 1];
    s[threadIdx.x] = acc;
    __syncthreads();
    for (int off = 128; off > 0; off >>= 1) {
        if (threadIdx.x < off) s[threadIdx.x] |= s[threadIdx.x + off];
        __syncthreads();
    }
    if (threadIdx.x == 0) g_is64 = (s[0] == 0) ? 1 : 0;
}

// ---------------- graph prep ----------------
__global__ void k_zero_counts() {
    int i = blockIdx.x * blockDim.x + threadIdx.x;
    if (i < N_NODES) { g_cnt[i] = 0; g_cnt2[i] = 0; }
}

__global__ void k_count(const void* __restrict__ ei) {
    int e = blockIdx.x * blockDim.x + threadIdx.x;
    if (e < N_EDGES) {
        int d = edge_at(ei, (long long)N_EDGES + e);
        if (d >= 0 && d < N_NODES) atomicAdd(&g_cnt[d], 1);
    }
}

__global__ void k_dinv() {
    int i = blockIdx.x * blockDim.x + threadIdx.x;
    if (i < N_NODES) g_dinv[i] = rsqrtf((float)g_cnt[i] + 1.0f);
}

__global__ void k_scan() {
    const int T = 1024;
    int tid = threadIdx.x;
    const int chunk = (N_NODES + T - 1) / T;
    int beg = tid * chunk;
    int end = min(beg + chunk, N_NODES);
    int sum = 0;
    for (int i = beg; i < end; i++) sum += g_cnt[i];
    __shared__ int s[T];
    s[tid] = sum;
    __syncthreads();
    for (int off = 1; off < T; off <<= 1) {
        int v = (tid >= off) ? s[tid - off] : 0;
        __syncthreads();
        s[tid] += v;
        __syncthreads();
    }
    int run = (tid > 0) ? s[tid - 1] : 0;
    for (int i = beg; i < end; i++) { g_rowptr[i] = run; run += g_cnt[i]; }
    if (tid == T - 1) g_rowptr[N_NODES] = N_EDGES;
}

__global__ void k_scatter(const void* __restrict__ ei) {
    int e = blockIdx.x * blockDim.x + threadIdx.x;
    if (e < N_EDGES) {
        int s = edge_at(ei, e);
        int d = edge_at(ei, (long long)N_EDGES + e);
        if (s < 0 || s >= N_NODES || d < 0 || d >= N_NODES) return;
        int pos = g_rowptr[d] + atomicAdd(&g_cnt2[d], 1);
        if (pos >= 0 && pos < N_EDGES) {
            g_colsrc[pos] = s;
            g_norm[pos] = g_dinv[s] * g_dinv[d];
        }
    }
}

// ---------------- operand pre-split ----------------
__global__ void k_split_x(const float* __restrict__ x) {
    size_t i = (size_t)blockIdx.x * blockDim.x + threadIdx.x;
    const size_t total4 = (size_t)N_NODES * C_IN / 4;
    if (i >= total4) return;
    float4 v = ((const float4*)x)[i];
    bf16 h[4], l[4];
    split_bf16(v.x, h[0], l[0]); split_bf16(v.y, h[1], l[1]);
    split_bf16(v.z, h[2], l[2]); split_bf16(v.w, h[3], l[3]);
    ((__nv_bfloat162*)g_Hh)[2 * i]     = __nv_bfloat162(h[0], h[1]);
    ((__nv_bfloat162*)g_Hh)[2 * i + 1] = __nv_bfloat162(h[2], h[3]);
    ((__nv_bfloat162*)g_Hl)[2 * i]     = __nv_bfloat162(l[0], l[1]);
    ((__nv_bfloat162*)g_Hl)[2 * i + 1] = __nv_bfloat162(l[2], l[3]);
}

// W[K][N] fp32 -> Wt_h/Wt_l [N][K] bf16 (transposed)
__global__ void k_split_w(const float* __restrict__ W, int K, int N, int sel) {
    bf16 *Wh, *Wl;
    if (sel == 0)      { Wh = g_W1h; Wl = g_W1l; }
    else if (sel == 1) { Wh = g_Wrh; Wl = g_Wrl; }
    else               { Wh = g_Wxh; Wl = g_Wxl; }
    int idx = blockIdx.x * blockDim.x + threadIdx.x;
    if (idx >= K * N) return;
    int n = idx / K, k = idx % K;
    bf16 h, l;
    split_bf16(W[(size_t)k * N + n], h, l);
    Wh[(size_t)n * K + k] = h;
    Wl[(size_t)n * K + k] = l;
}

// ---------------- tensor-core GEMM (pre-split bf16, cp.async double buffer) ----------------
#define BM 128
#define BN 64
#define BK 32
#define AST (BK + 8)    // 40 bf16 row stride = 80B (16B-aligned, conflict-free)

__device__ __forceinline__ void mma_bf16(float* c, const unsigned* a, const unsigned* b) {
    asm volatile(
        "mma.sync.aligned.m16n8k16.row.col.f32.bf16.bf16.f32 "
        "{%0,%1,%2,%3}, {%4,%5,%6,%7}, {%8,%9}, {%0,%1,%2,%3};"
        : "+f"(c[0]), "+f"(c[1]), "+f"(c[2]), "+f"(c[3])
        : "r"(a[0]), "r"(a[1]), "r"(a[2]), "r"(a[3]), "r"(b[0]), "r"(b[1]));
}

__device__ __forceinline__ void cp16(void* dst, const void* src, bool valid) {
    unsigned d = (unsigned)__cvta_generic_to_shared(dst);
    int sz = valid ? 16 : 0;
    asm volatile("cp.async.ca.shared.global [%0], [%1], 16, %2;\n"
                 :: "r"(d), "l"(src), "r"(sz));
}
__device__ __forceinline__ void cp_commit() { asm volatile("cp.async.commit_group;"); }
template <int NG>
__device__ __forceinline__ void cp_wait() { asm volatile("cp.async.wait_group %0;" :: "n"(NG)); }

__global__ void __launch_bounds__(256)
k_gemm_bf16(int wsel, int M, int N, int K) {
    const bf16* Ah = g_Hh;
    const bf16* Al = g_Hl;
    const bf16 *Bh, *Bl;
    if (wsel == 0)      { Bh = g_W1h; Bl = g_W1l; }
    else if (wsel == 1) { Bh = g_Wrh; Bl = g_Wrl; }
    else                { Bh = g_Wxh; Bl = g_Wxl; }
    float* C = g_T;

    extern __shared__ char smem[];
    bf16* sAh = (bf16*)smem;                 // [2][BM][AST]
    bf16* sAl = sAh + 2 * BM * AST;
    bf16* sBh = sAl + 2 * BM * AST;          // [2][BN][AST]
    bf16* sBl = sBh + 2 * BN * AST;

    int tid  = threadIdx.x;
    int w    = tid >> 5;
    int lane = tid & 31;
    int g    = lane >> 2;
    int t    = lane & 3;

    int row0 = blockIdx.y * BM;
    int col0 = blockIdx.x * BN;
    int wrow = w * 16;

    float acc[8][4];
#pragma unroll
    for (int n = 0; n < 8; n++)
#pragma unroll
        for (int j = 0; j < 4; j++) acc[n][j] = 0.0f;

    auto prefetch = [&](int st, int kt) {
#pragma unroll
        for (int it = 0; it < 2; it++) {
            int idx = tid + it * 256;
            int r = idx >> 2, c16 = idx & 3;
            bool v = (row0 + r) < M;
            size_t goff = (size_t)(row0 + r) * K + kt + c16 * 8;
            int soff = st * BM * AST + r * AST + c16 * 8;
            cp16(&sAh[soff], Ah + goff, v);
            cp16(&sAl[soff], Al + goff, v);
        }
        {
            int r = tid >> 2, c16 = tid & 3;
            size_t goff = (size_t)(col0 + r) * K + kt + c16 * 8;
            int soff = st * BN * AST + r * AST + c16 * 8;
            cp16(&sBh[soff], Bh + goff, true);
            cp16(&sBl[soff], Bl + goff, true);
        }
    };

    const int nk = K / BK;
    prefetch(0, 0);
    cp_commit();

    for (int ik = 0; ik < nk; ik++) {
        int cur = ik & 1;
        if (ik + 1 < nk) {
            prefetch(cur ^ 1, (ik + 1) * BK);
            cp_commit();
            cp_wait<1>();
        } else {
            cp_wait<0>();
        }
        __syncthreads();

        const bf16* pAh = sAh + cur * BM * AST;
        const bf16* pAl = sAl + cur * BM * AST;
        const bf16* pBh = sBh + cur * BN * AST;
        const bf16* pBl = sBl + cur * BN * AST;

#pragma unroll
        for (int ks = 0; ks < BK; ks += 16) {
            unsigned ah[4], al[4];
            ah[0] = *(const unsigned*)&pAh[(wrow + g    ) * AST + ks + 2*t    ];
            ah[1] = *(const unsigned*)&pAh[(wrow + g + 8) * AST + ks + 2*t    ];
            ah[2] = *(const unsigned*)&pAh[(wrow + g    ) * AST + ks + 2*t + 8];
            ah[3] = *(const unsigned*)&pAh[(wrow + g + 8) * AST + ks + 2*t + 8];
            al[0] = *(const unsigned*)&pAl[(wrow + g    ) * AST + ks + 2*t    ];
            al[1] = *(const unsigned*)&pAl[(wrow + g + 8) * AST + ks + 2*t    ];
            al[2] = *(const unsigned*)&pAl[(wrow + g    ) * AST + ks + 2*t + 8];
            al[3] = *(const unsigned*)&pAl[(wrow + g + 8) * AST + ks + 2*t + 8];
#pragma unroll
            for (int n = 0; n < 8; n++) {
                unsigned bh[2], bl[2];
                bh[0] = *(const unsigned*)&pBh[(n*8 + g) * AST + ks + 2*t    ];
                bh[1] = *(const unsigned*)&pBh[(n*8 + g) * AST + ks + 2*t + 8];
                bl[0] = *(const unsigned*)&pBl[(n*8 + g) * AST + ks + 2*t    ];
                bl[1] = *(const unsigned*)&pBl[(n*8 + g) * AST + ks + 2*t + 8];
                mma_bf16(acc[n], ah, bh);
                mma_bf16(acc[n], ah, bl);
                mma_bf16(acc[n], al, bh);
            }
        }
        __syncthreads();
    }

#pragma unroll
    for (int n = 0; n < 8; n++) {
        int col = col0 + n * 8 + 2 * t;
        int r0 = row0 + wrow + g;
        int r1 = r0 + 8;
        if (r0 < M) {
            C[(size_t)r0 * N + col]     = acc[n][0];
            C[(size_t)r0 * N + col + 1] = acc[n][1];
        }
        if (r1 < M) {
            C[(size_t)r1 * N + col]     = acc[n][2];
            C[(size_t)r1 * N + col + 1] = acc[n][3];
        }
    }
}

// ---------------- CSR SpMM with fused epilogue (+ bf16 split of H) ----------------
template <int C, bool RELU, bool RES, bool TO_OUT>
__global__ void k_spmm(const float* __restrict__ bias, float* __restrict__ out) {
    constexpr int V4 = C / 4;
    int i = blockIdx.x;
    int tid = threadIdx.x;
    const float4* T4 = (const float4*)g_T;

    float di = g_dinv[i];
    float wself = di * di;
    float4 tv = T4[(size_t)i * V4 + tid];
    float4 acc = make_float4(tv.x * wself, tv.y * wself, tv.z * wself, tv.w * wself);

    int e = g_rowptr[i];
    int end = g_rowptr[i + 1];
    for (; e < end; e++) {
        int s = g_colsrc[e];
        float w = g_norm[e];
        float4 v = T4[(size_t)s * V4 + tid];
        acc.x += w * v.x; acc.y += w * v.y; acc.z += w * v.z; acc.w += w * v.w;
    }

    float4 b = ((const float4*)bias)[tid];
    acc.x += b.x; acc.y += b.y; acc.z += b.z; acc.w += b.w;

    if (RELU) {
        acc.x = fmaxf(acc.x, 0.f); acc.y = fmaxf(acc.y, 0.f);
        acc.z = fmaxf(acc.z, 0.f); acc.w = fmaxf(acc.w, 0.f);
    }
    if (RES) {
        float4 h = ((const float4*)g_H)[(size_t)i * V4 + tid];
        acc.x += h.x; acc.y += h.y; acc.z += h.z; acc.w += h.w;
    }

    if (TO_OUT) {
        ((float4*)out)[(size_t)i * V4 + tid] = acc;
    } else {
        size_t o4 = (size_t)i * V4 + tid;
        ((float4*)g_H)[o4] = acc;
        bf16 h[4], l[4];
        split_bf16(acc.x, h[0], l[0]); split_bf16(acc.y, h[1], l[1]);
        split_bf16(acc.z, h[2], l[2]); split_bf16(acc.w, h[3], l[3]);
        ((__nv_bfloat162*)g_Hh)[2 * o4]     = __nv_bfloat162(h[0], h[1]);
        ((__nv_bfloat162*)g_Hh)[2 * o4 + 1] = __nv_bfloat162(h[2], h[3]);
        ((__nv_bfloat162*)g_Hl)[2 * o4]     = __nv_bfloat162(l[0], l[1]);
        ((__nv_bfloat162*)g_Hl)[2 * o4 + 1] = __nv_bfloat162(l[2], l[3]);
    }
}

// ---------------- launch ----------------
extern "C" void kernel_launch(void* const* d_in, const int* in_sizes, int n_in,
                              void* d_out, int out_size) {
    const float* x  = (const float*)d_in[0];
    const void*  ei = d_in[1];
    const float* W1 = (const float*)d_in[2];
    const float* b1 = (const float*)d_in[3];
    const float* Wr = (const float*)d_in[4];
    const float* br = (const float*)d_in[5];
    const float* Wx = (const float*)d_in[6];
    const float* bx = (const float*)d_in[7];
    float* out      = (float*)d_out;

    const int GSMEM = 2 * (2 * BM * AST + 2 * BN * AST) * (int)sizeof(bf16);  // 61440
    cudaFuncSetAttribute(k_gemm_bf16, cudaFuncAttributeMaxDynamicSharedMemorySize, GSMEM);

    // graph prep
    k_detect<<<1, 256>>>(ei);
    k_zero_counts<<<(N_NODES + 255) / 256, 256>>>();
    k_count<<<(N_EDGES + 255) / 256, 256>>>(ei);
    k_dinv<<<(N_NODES + 255) / 256, 256>>>();
    k_scan<<<1, 1024>>>();
    k_scatter<<<(N_EDGES + 255) / 256, 256>>>(ei);

    // operand pre-split
    k_split_w<<<(C_IN * C_H1 + 255) / 256, 256>>>(W1, C_IN, C_H1, 0);
    k_split_w<<<(C_H1 * C_H1 + 255) / 256, 256>>>(Wr, C_H1, C_H1, 1);
    k_split_w<<<(C_H1 * C_OUT + 255) / 256, 256>>>(Wx, C_H1, C_OUT, 2);
    k_split_x<<<((N_NODES * C_IN / 4) + 255) / 256, 256>>>(x);

    dim3 g512(C_H1 / BN, (N_NODES + BM - 1) / BM);
    dim3 g256(C_OUT / BN, (N_NODES + BM - 1) / BM);

    // layer 0: H = relu(agg(x @ W1) + b1)
    k_gemm_bf16<<<g512, 256, GSMEM>>>(0, N_NODES, C_H1, C_IN);
    k_spmm<C_H1, true, false, false><<<N_NODES, C_H1 / 4>>>(b1, out);

    // 4 residual layers
    for (int l = 0; l < 4; l++) {
        k_gemm_bf16<<<g512, 256, GSMEM>>>(1, N_NODES, C_H1, C_H1);
        k_spmm<C_H1, true, true, false><<<N_NODES, C_H1 / 4>>>(br, out);
    }

    // final: out = agg(H @ Wx) + bx
    k_gemm_bf16<<<g256, 256, GSMEM>>>(2, N_NODES, C_OUT, C_H1);
    k_spmm<C_OUT, false, false, true><<<N_NODES, C_OUT / 4>>>(bx, out);
}

// round 10
// speedup vs baseline: 2.0156x; 1.2421x over previous
#include <cuda_runtime.h>
#include <cuda_bf16.h>

#define N_NODES 50000
#define N_EDGES 800000
#define C_IN   512
#define C_H1   512
#define C_OUT  256

typedef __nv_bfloat16 bf16;

// ---------------- device scratch (no allocations allowed) ----------------
__device__ __align__(16) float g_T[(size_t)N_NODES * C_H1];   // GEMM output
__device__ __align__(16) float g_H[(size_t)N_NODES * C_H1];   // hidden (fp32, for residual)
__device__ __align__(16) bf16  g_Hh[(size_t)N_NODES * C_H1];  // hidden hi (GEMM A)
__device__ __align__(16) bf16  g_Hl[(size_t)N_NODES * C_H1];  // hidden lo
__device__ __align__(16) bf16  g_W1h[C_IN * C_H1],  g_W1l[C_IN * C_H1];   // [N][K] transposed
__device__ __align__(16) bf16  g_Wrh[C_H1 * C_H1],  g_Wrl[C_H1 * C_H1];
__device__ __align__(16) bf16  g_Wxh[C_H1 * C_OUT], g_Wxl[C_H1 * C_OUT];
__device__ float g_dinv[N_NODES];
__device__ int   g_cnt[N_NODES];
__device__ int   g_cnt2[N_NODES];
__device__ int   g_rowptr[N_NODES + 1];
__device__ int   g_colsrc[N_EDGES];
__device__ float g_norm[N_EDGES];
__device__ int   g_is64;

__device__ __forceinline__ int edge_at(const void* ei, long long idx) {
    if (g_is64) return (int)((const long long*)ei)[idx];
    return ((const int*)ei)[idx];
}

__device__ __forceinline__ void split_bf16(float v, bf16& hi, bf16& lo) {
    hi = __float2bfloat16(v);
    lo = __float2bfloat16(v - __bfloat162float(hi));
}

// ---------------- dtype sniffer (parallel) ----------------
__global__ void k_detect(const void* ei) {
    const int* w = (const int*)ei;
    __shared__ unsigned s[256];
    unsigned acc = 0;
    for (int i = threadIdx.x; i < 2048; i += 256) acc |= (unsigned)w[2 * i + 1];
    s[threadIdx.x] = acc;
    __syncthreads();
    for (int off = 128; off > 0; off >>= 1) {
        if (threadIdx.x < off) s[threadIdx.x] |= s[threadIdx.x + off];
        __syncthreads();
    }
    if (threadIdx.x == 0) g_is64 = (s[0] == 0) ? 1 : 0;
}

// ---------------- graph prep ----------------
__global__ void k_zero_counts() {
    int i = blockIdx.x * blockDim.x + threadIdx.x;
    if (i < N_NODES) { g_cnt[i] = 0; g_cnt2[i] = 0; }
}

__global__ void k_count(const void* __restrict__ ei) {
    int e = blockIdx.x * blockDim.x + threadIdx.x;
    if (e < N_EDGES) {
        int d = edge_at(ei, (long long)N_EDGES + e);
        if (d >= 0 && d < N_NODES) atomicAdd(&g_cnt[d], 1);
    }
}

__global__ void k_dinv() {
    int i = blockIdx.x * blockDim.x + threadIdx.x;
    if (i < N_NODES) g_dinv[i] = rsqrtf((float)g_cnt[i] + 1.0f);
}

__global__ void k_scan() {
    const int T = 1024;
    int tid = threadIdx.x;
    const int chunk = (N_NODES + T - 1) / T;
    int beg = tid * chunk;
    int end = min(beg + chunk, N_NODES);
    int sum = 0;
    for (int i = beg; i < end; i++) sum += g_cnt[i];
    __shared__ int s[T];
    s[tid] = sum;
    __syncthreads();
    for (int off = 1; off < T; off <<= 1) {
        int v = (tid >= off) ? s[tid - off] : 0;
        __syncthreads();
        s[tid] += v;
        __syncthreads();
    }
    int run = (tid > 0) ? s[tid - 1] : 0;
    for (int i = beg; i < end; i++) { g_rowptr[i] = run; run += g_cnt[i]; }
    if (tid == T - 1) g_rowptr[N_NODES] = N_EDGES;
}

__global__ void k_scatter(const void* __restrict__ ei) {
    int e = blockIdx.x * blockDim.x + threadIdx.x;
    if (e < N_EDGES) {
        int s = edge_at(ei, e);
        int d = edge_at(ei, (long long)N_EDGES + e);
        if (s < 0 || s >= N_NODES || d < 0 || d >= N_NODES) return;
        int pos = g_rowptr[d] + atomicAdd(&g_cnt2[d], 1);
        if (pos >= 0 && pos < N_EDGES) {
            g_colsrc[pos] = s;
            g_norm[pos] = g_dinv[s] * g_dinv[d];
        }
    }
}

// ---------------- operand pre-split ----------------
__global__ void k_split_x(const float* __restrict__ x) {
    size_t i = (size_t)blockIdx.x * blockDim.x + threadIdx.x;
    const size_t total4 = (size_t)N_NODES * C_IN / 4;
    if (i >= total4) return;
    float4 v = ((const float4*)x)[i];
    bf16 h[4], l[4];
    split_bf16(v.x, h[0], l[0]); split_bf16(v.y, h[1], l[1]);
    split_bf16(v.z, h[2], l[2]); split_bf16(v.w, h[3], l[3]);
    ((__nv_bfloat162*)g_Hh)[2 * i]     = __nv_bfloat162(h[0], h[1]);
    ((__nv_bfloat162*)g_Hh)[2 * i + 1] = __nv_bfloat162(h[2], h[3]);
    ((__nv_bfloat162*)g_Hl)[2 * i]     = __nv_bfloat162(l[0], l[1]);
    ((__nv_bfloat162*)g_Hl)[2 * i + 1] = __nv_bfloat162(l[2], l[3]);
}

// W[K][N] fp32 -> Wt_h/Wt_l [N][K] bf16 (transposed)
__global__ void k_split_w(const float* __restrict__ W, int K, int N, int sel) {
    bf16 *Wh, *Wl;
    if (sel == 0)      { Wh = g_W1h; Wl = g_W1l; }
    else if (sel == 1) { Wh = g_Wrh; Wl = g_Wrl; }
    else               { Wh = g_Wxh; Wl = g_Wxl; }
    int idx = blockIdx.x * blockDim.x + threadIdx.x;
    if (idx >= K * N) return;
    int n = idx / K, k = idx % K;
    bf16 h, l;
    split_bf16(W[(size_t)k * N + n], h, l);
    Wh[(size_t)n * K + k] = h;
    Wl[(size_t)n * K + k] = l;
}

// ---------------- tensor-core GEMM ----------------
// 4 warps x (32x64) warp tile, BM=128 BN=64 BK=32, ldmatrix fragments,
// cp.async double buffer. bf16x3: acc += ah*bh + ah*bl + al*bh.
#define BM 128
#define BN 64
#define BK 32
#define AST (BK + 8)    // 40 bf16 row stride = 80B (16B-aligned; 20r mod 32 banks disjoint)

__device__ __forceinline__ void mma_bf16(float* c, const unsigned* a, const unsigned* b) {
    asm volatile(
        "mma.sync.aligned.m16n8k16.row.col.f32.bf16.bf16.f32 "
        "{%0,%1,%2,%3}, {%4,%5,%6,%7}, {%8,%9}, {%0,%1,%2,%3};"
        : "+f"(c[0]), "+f"(c[1]), "+f"(c[2]), "+f"(c[3])
        : "r"(a[0]), "r"(a[1]), "r"(a[2]), "r"(a[3]), "r"(b[0]), "r"(b[1]));
}

__device__ __forceinline__ void ldsm4(unsigned* r, unsigned addr) {
    asm volatile("ldmatrix.sync.aligned.m8n8.x4.shared.b16 {%0,%1,%2,%3}, [%4];"
                 : "=r"(r[0]), "=r"(r[1]), "=r"(r[2]), "=r"(r[3]) : "r"(addr));
}

__device__ __forceinline__ void cp16(void* dst, const void* src, bool valid) {
    unsigned d = (unsigned)__cvta_generic_to_shared(dst);
    int sz = valid ? 16 : 0;
    asm volatile("cp.async.ca.shared.global [%0], [%1], 16, %2;\n"
                 :: "r"(d), "l"(src), "r"(sz));
}
__device__ __forceinline__ void cp_commit() { asm volatile("cp.async.commit_group;"); }
template <int NG>
__device__ __forceinline__ void cp_wait() { asm volatile("cp.async.wait_group %0;" :: "n"(NG)); }

__global__ void __launch_bounds__(128)
k_gemm_bf16(int wsel, int M, int N, int K) {
    const bf16* Ah = g_Hh;
    const bf16* Al = g_Hl;
    const bf16 *Bh, *Bl;
    if (wsel == 0)      { Bh = g_W1h; Bl = g_W1l; }
    else if (wsel == 1) { Bh = g_Wrh; Bl = g_Wrl; }
    else                { Bh = g_Wxh; Bl = g_Wxl; }
    float* C = g_T;

    extern __shared__ char smem[];
    bf16* sAh = (bf16*)smem;                 // [2][BM][AST]
    bf16* sAl = sAh + 2 * BM * AST;
    bf16* sBh = sAl + 2 * BM * AST;          // [2][BN][AST]
    bf16* sBl = sBh + 2 * BN * AST;

    int tid  = threadIdx.x;
    int w    = tid >> 5;
    int lane = tid & 31;

    int row0 = blockIdx.y * BM;
    int col0 = blockIdx.x * BN;
    int wrow = w * 32;

    // ldmatrix per-lane offsets (element units)
    int a_r = (lane & 7) + ((lane >> 3) & 1) * 8;   // + wrow + mg*16
    int a_c = (lane >> 4) * 8;                       // + ks
    int b_r = (lane & 7) + (lane >> 4) * 8;          // + 16*p
    int b_c = ((lane >> 3) & 1) * 8;                 // + ks

    unsigned uAh = (unsigned)__cvta_generic_to_shared(sAh);
    unsigned uAl = (unsigned)__cvta_generic_to_shared(sAl);
    unsigned uBh = (unsigned)__cvta_generic_to_shared(sBh);
    unsigned uBl = (unsigned)__cvta_generic_to_shared(sBl);

    float acc[2][8][4];
#pragma unroll
    for (int mg = 0; mg < 2; mg++)
#pragma unroll
        for (int n = 0; n < 8; n++)
#pragma unroll
            for (int j = 0; j < 4; j++) acc[mg][n][j] = 0.0f;

    auto prefetch = [&](int st, int kt) {
        // A: 128 rows x 4 chunks (16B) x {h,l} -> 512 pairs / 128 thr = 4 iters
#pragma unroll
        for (int it = 0; it < 4; it++) {
            int idx = tid + it * 128;
            int r = idx >> 2, c16 = idx & 3;
            bool v = (row0 + r) < M;
            size_t goff = (size_t)(row0 + r) * K + kt + c16 * 8;
            int soff = st * BM * AST + r * AST + c16 * 8;
            cp16(&sAh[soff], Ah + goff, v);
            cp16(&sAl[soff], Al + goff, v);
        }
        // B: 64 rows x 4 chunks x {h,l} -> 256 pairs / 128 thr = 2 iters
#pragma unroll
        for (int it = 0; it < 2; it++) {
            int idx = tid + it * 128;
            int r = idx >> 2, c16 = idx & 3;
            size_t goff = (size_t)(col0 + r) * K + kt + c16 * 8;
            int soff = st * BN * AST + r * AST + c16 * 8;
            cp16(&sBh[soff], Bh + goff, true);
            cp16(&sBl[soff], Bl + goff, true);
        }
    };

    const int nk = K / BK;
    prefetch(0, 0);
    cp_commit();

    for (int ik = 0; ik < nk; ik++) {
        int cur = ik & 1;
        if (ik + 1 < nk) {
            prefetch(cur ^ 1, (ik + 1) * BK);
            cp_commit();
            cp_wait<1>();
        } else {
            cp_wait<0>();
        }
        __syncthreads();

        int aBase = cur * BM * AST;
        int bBase = cur * BN * AST;

#pragma unroll
        for (int ks = 0; ks < BK; ks += 16) {
            unsigned ah[2][4], al[2][4];
#pragma unroll
            for (int mg = 0; mg < 2; mg++) {
                int off = aBase + (wrow + mg * 16 + a_r) * AST + ks + a_c;
                ldsm4(ah[mg], uAh + off * 2);
                ldsm4(al[mg], uAl + off * 2);
            }
#pragma unroll
            for (int p = 0; p < 4; p++) {
                unsigned bh[4], bl[4];
                int off = bBase + (16 * p + b_r) * AST + ks + b_c;
                ldsm4(bh, uBh + off * 2);
                ldsm4(bl, uBl + off * 2);
#pragma unroll
                for (int mg = 0; mg < 2; mg++) {
                    mma_bf16(acc[mg][2 * p],     ah[mg], bh);
                    mma_bf16(acc[mg][2 * p],     ah[mg], bl);
                    mma_bf16(acc[mg][2 * p],     al[mg], bh);
                    mma_bf16(acc[mg][2 * p + 1], ah[mg], bh + 2);
                    mma_bf16(acc[mg][2 * p + 1], ah[mg], bl + 2);
                    mma_bf16(acc[mg][2 * p + 1], al[mg], bh + 2);
                }
            }
        }
        __syncthreads();
    }

    // epilogue
#pragma unroll
    for (int mg = 0; mg < 2; mg++) {
        int r0 = row0 + wrow + mg * 16 + (lane >> 2);
#pragma unroll
        for (int n = 0; n < 8; n++) {
            int col = col0 + n * 8 + 2 * (lane & 3);
            if (r0 < M)
                *(float2*)&C[(size_t)r0 * N + col] = make_float2(acc[mg][n][0], acc[mg][n][1]);
            if (r0 + 8 < M)
                *(float2*)&C[(size_t)(r0 + 8) * N + col] = make_float2(acc[mg][n][2], acc[mg][n][3]);
        }
    }
}

// ---------------- CSR SpMM with fused epilogue (+ bf16 split of H) ----------------
template <int C, bool RELU, bool RES, bool TO_OUT>
__global__ void k_spmm(const float* __restrict__ bias, float* __restrict__ out) {
    constexpr int V4 = C / 4;
    int i = blockIdx.x;
    int tid = threadIdx.x;
    const float4* T4 = (const float4*)g_T;

    float di = g_dinv[i];
    float wself = di * di;
    float4 tv = T4[(size_t)i * V4 + tid];
    float4 acc = make_float4(tv.x * wself, tv.y * wself, tv.z * wself, tv.w * wself);

    int e = g_rowptr[i];
    int end = g_rowptr[i + 1];
    // unroll-4: batch index loads so 4 row gathers are in flight
    for (; e + 4 <= end; e += 4) {
        int   s0 = g_colsrc[e],     s1 = g_colsrc[e + 1];
        int   s2 = g_colsrc[e + 2], s3 = g_colsrc[e + 3];
        float w0 = g_norm[e],       w1 = g_norm[e + 1];
        float w2 = g_norm[e + 2],   w3 = g_norm[e + 3];
        float4 v0 = T4[(size_t)s0 * V4 + tid];
        float4 v1 = T4[(size_t)s1 * V4 + tid];
        float4 v2 = T4[(size_t)s2 * V4 + tid];
        float4 v3 = T4[(size_t)s3 * V4 + tid];
        acc.x += w0 * v0.x + w1 * v1.x + w2 * v2.x + w3 * v3.x;
        acc.y += w0 * v0.y + w1 * v1.y + w2 * v2.y + w3 * v3.y;
        acc.z += w0 * v0.z + w1 * v1.z + w2 * v2.z + w3 * v3.z;
        acc.w += w0 * v0.w + w1 * v1.w + w2 * v2.w + w3 * v3.w;
    }
    for (; e < end; e++) {
        int s = g_colsrc[e];
        float wgt = g_norm[e];
        float4 v = T4[(size_t)s * V4 + tid];
        acc.x += wgt * v.x; acc.y += wgt * v.y; acc.z += wgt * v.z; acc.w += wgt * v.w;
    }

    float4 b = ((const float4*)bias)[tid];
    acc.x += b.x; acc.y += b.y; acc.z += b.z; acc.w += b.w;

    if (RELU) {
        acc.x = fmaxf(acc.x, 0.f); acc.y = fmaxf(acc.y, 0.f);
        acc.z = fmaxf(acc.z, 0.f); acc.w = fmaxf(acc.w, 0.f);
    }
    if (RES) {
        float4 h = ((const float4*)g_H)[(size_t)i * V4 + tid];
        acc.x += h.x; acc.y += h.y; acc.z += h.z; acc.w += h.w;
    }

    if (TO_OUT) {
        ((float4*)out)[(size_t)i * V4 + tid] = acc;
    } else {
        size_t o4 = (size_t)i * V4 + tid;
        ((float4*)g_H)[o4] = acc;
        bf16 h[4], l[4];
        split_bf16(acc.x, h[0], l[0]); split_bf16(acc.y, h[1], l[1]);
        split_bf16(acc.z, h[2], l[2]); split_bf16(acc.w, h[3], l[3]);
        ((__nv_bfloat162*)g_Hh)[2 * o4]     = __nv_bfloat162(h[0], h[1]);
        ((__nv_bfloat162*)g_Hh)[2 * o4 + 1] = __nv_bfloat162(h[2], h[3]);
        ((__nv_bfloat162*)g_Hl)[2 * o4]     = __nv_bfloat162(l[0], l[1]);
        ((__nv_bfloat162*)g_Hl)[2 * o4 + 1] = __nv_bfloat162(l[2], l[3]);
    }
}

// ---------------- launch ----------------
extern "C" void kernel_launch(void* const* d_in, const int* in_sizes, int n_in,
                              void* d_out, int out_size) {
    const float* x  = (const float*)d_in[0];
    const void*  ei = d_in[1];
    const float* W1 = (const float*)d_in[2];
    const float* b1 = (const float*)d_in[3];
    const float* Wr = (const float*)d_in[4];
    const float* br = (const float*)d_in[5];
    const float* Wx = (const float*)d_in[6];
    const float* bx = (const float*)d_in[7];
    float* out      = (float*)d_out;

    const int GSMEM = 2 * (2 * BM * AST + 2 * BN * AST) * (int)sizeof(bf16);  // 61440
    cudaFuncSetAttribute(k_gemm_bf16, cudaFuncAttributeMaxDynamicSharedMemorySize, GSMEM);

    // graph prep
    k_detect<<<1, 256>>>(ei);
    k_zero_counts<<<(N_NODES + 255) / 256, 256>>>();
    k_count<<<(N_EDGES + 255) / 256, 256>>>(ei);
    k_dinv<<<(N_NODES + 255) / 256, 256>>>();
    k_scan<<<1, 1024>>>();
    k_scatter<<<(N_EDGES + 255) / 256, 256>>>(ei);

    // operand pre-split
    k_split_w<<<(C_IN * C_H1 + 255) / 256, 256>>>(W1, C_IN, C_H1, 0);
    k_split_w<<<(C_H1 * C_H1 + 255) / 256, 256>>>(Wr, C_H1, C_H1, 1);
    k_split_w<<<(C_H1 * C_OUT + 255) / 256, 256>>>(Wx, C_H1, C_OUT, 2);
    k_split_x<<<((N_NODES * C_IN / 4) + 255) / 256, 256>>>(x);

    dim3 g512(C_H1 / BN, (N_NODES + BM - 1) / BM);
    dim3 g256(C_OUT / BN, (N_NODES + BM - 1) / BM);

    // layer 0: H = relu(agg(x @ W1) + b1)
    k_gemm_bf16<<<g512, 128, GSMEM>>>(0, N_NODES, C_H1, C_IN);
    k_spmm<C_H1, true, false, false><<<N_NODES, C_H1 / 4>>>(b1, out);

    // 4 residual layers
    for (int l = 0; l < 4; l++) {
        k_gemm_bf16<<<g512, 128, GSMEM>>>(1, N_NODES, C_H1, C_H1);
        k_spmm<C_H1, true, true, false><<<N_NODES, C_H1 / 4>>>(br, out);
    }

    // final: out = agg(H @ Wx) + bx
    k_gemm_bf16<<<g256, 128, GSMEM>>>(2, N_NODES, C_OUT, C_H1);
    k_spmm<C_OUT, false, false, true><<<N_NODES, C_OUT / 4>>>(bx, out);
}